// round 2
// baseline (speedup 1.0000x reference)
#include <cuda_runtime.h>
#include <cstdint>

#define NV 500000
#define NC 250000
#define NE 8000000
#define F  16

// ---------------- scratch (device globals: no allocation allowed) ----------------
__device__ __align__(16) float g_colsum[NC];
__device__ __align__(16) float g_cons1[NC * F];
__device__ __align__(16) float g_cons2[NC * F];
__device__ __align__(16) float g_v2c2[NC * F];
__device__ __align__(16) float g_c2v1[NV * F];
__device__ __align__(16) float g_c2v2[NV * F];
__device__ __align__(16) float g_vars1[NV * F];

// ---------------- helpers ----------------
__device__ __forceinline__ void red_add_v4(float* a, float4 v) {
    asm volatile("red.global.add.v4.f32 [%0], {%1,%2,%3,%4};"
                 :: "l"(a), "f"(v.x), "f"(v.y), "f"(v.z), "f"(v.w) : "memory");
}

// JAX threefry2x32 with key = (0, 42)  (jax.random.key(42))
__device__ __forceinline__ void threefry_0_42(uint32_t x0, uint32_t x1,
                                              uint32_t& o0, uint32_t& o1) {
    const uint32_t k0 = 0u, k1 = 42u;
    const uint32_t k2 = 0x1BD11BDAu ^ k0 ^ k1;
    x0 += k0; x1 += k1;
#define TFR(r) { x0 += x1; x1 = (x1 << (r)) | (x1 >> (32 - (r))); x1 ^= x0; }
    TFR(13) TFR(15) TFR(26) TFR(6)   x0 += k1; x1 += k2 + 1u;
    TFR(17) TFR(29) TFR(16) TFR(24)  x0 += k2; x1 += k0 + 2u;
    TFR(13) TFR(15) TFR(26) TFR(6)   x0 += k0; x1 += k1 + 3u;
    TFR(17) TFR(29) TFR(16) TFR(24)  x0 += k1; x1 += k2 + 4u;
    TFR(13) TFR(15) TFR(26) TFR(6)   x0 += k2; x1 += k0 + 5u;
#undef TFR
    o0 = x0; o1 = x1;
}

// XLA f32 ErfInv (Giles polynomial), matching lax.erf_inv
__device__ __forceinline__ float erfinv_xla(float x) {
    float w = -log1pf(-x * x);
    float p;
    if (w < 5.0f) {
        w -= 2.5f;
        p = 2.81022636e-08f;
        p = fmaf(p, w, 3.43273939e-07f);
        p = fmaf(p, w, -3.5233877e-06f);
        p = fmaf(p, w, -4.39150654e-06f);
        p = fmaf(p, w, 0.00021858087f);
        p = fmaf(p, w, -0.00125372503f);
        p = fmaf(p, w, -0.00417768164f);
        p = fmaf(p, w, 0.246640727f);
        p = fmaf(p, w, 1.50140941f);
    } else {
        w = sqrtf(w) - 3.0f;
        p = -0.000200214257f;
        p = fmaf(p, w, 0.000100950558f);
        p = fmaf(p, w, 0.00134934322f);
        p = fmaf(p, w, -0.00367342844f);
        p = fmaf(p, w, 0.00573950773f);
        p = fmaf(p, w, -0.0076224613f);
        p = fmaf(p, w, 0.00943887047f);
        p = fmaf(p, w, 1.00167406f);
        p = fmaf(p, w, 2.83297682f);
    }
    return p * x;
}

__device__ __forceinline__ void load16(float* x, const float* __restrict__ p) {
    const float4* r = (const float4*)p;
    float4 a = r[0], b = r[1], c = r[2], d = r[3];
    x[0]=a.x; x[1]=a.y; x[2]=a.z; x[3]=a.w;
    x[4]=b.x; x[5]=b.y; x[6]=b.z; x[7]=b.w;
    x[8]=c.x; x[9]=c.y; x[10]=c.z; x[11]=c.w;
    x[12]=d.x; x[13]=d.y; x[14]=d.z; x[15]=d.w;
}

__device__ __forceinline__ void store16(float* __restrict__ p, const float* x) {
    float4* w = (float4*)p;
    w[0] = make_float4(x[0], x[1], x[2], x[3]);
    w[1] = make_float4(x[4], x[5], x[6], x[7]);
    w[2] = make_float4(x[8], x[9], x[10], x[11]);
    w[3] = make_float4(x[12], x[13], x[14], x[15]);
}

// ---------------- kernels ----------------

// Pass-1 v2c collapses to a scalar column-sum (variables == ones)
__global__ void k_colsum(const int* __restrict__ cols, const float* __restrict__ vals) {
    int i = blockIdx.x * blockDim.x + threadIdx.x;
    if (i < NE) atomicAdd(&g_colsum[cols[i]], vals[i]);
}

// constraints1[c][f] = relu(colsum[c]*swc[f] + bc[f]),  swc = column sums of bottom half of Wc
__global__ void k_cons1(const float* __restrict__ Wc, const float* __restrict__ bc) {
    __shared__ float sw[F], sb[F];
    if (threadIdx.x < F) {
        float s = 0.f;
#pragma unroll
        for (int j = 0; j < F; j++) s += Wc[(F + j) * F + threadIdx.x];
        sw[threadIdx.x] = s;
        sb[threadIdx.x] = bc[threadIdx.x];
    }
    __syncthreads();
    int c = blockIdx.x * blockDim.x + threadIdx.x;
    if (c >= NC) return;
    float cs = g_colsum[c];
    float o[F];
#pragma unroll
    for (int f = 0; f < F; f++) o[f] = fmaxf(fmaf(cs, sw[f], sb[f]), 0.f);
    store16(g_cons1 + (size_t)c * F, o);
}

// generic gather-scale-scatter SpMM step: out[dst] += val * tbl[src]
__global__ void k_spmm(const int* __restrict__ src, const int* __restrict__ dst,
                       const float* __restrict__ vals, const float* __restrict__ tbl,
                       float* __restrict__ out) {
    int e = blockIdx.x * blockDim.x + threadIdx.x;
    if (e >= NE) return;
    int s = src[e], d = dst[e];
    float v = vals[e];
    const float4* r = (const float4*)(tbl + (size_t)s * F);
    float4 a = r[0], b = r[1], c = r[2], w = r[3];
    a.x *= v; a.y *= v; a.z *= v; a.w *= v;
    b.x *= v; b.y *= v; b.z *= v; b.w *= v;
    c.x *= v; c.y *= v; c.z *= v; c.w *= v;
    w.x *= v; w.y *= v; w.z *= v; w.w *= v;
    float* o = out + (size_t)d * F;
    red_add_v4(o, a);
    red_add_v4(o + 4, b);
    red_add_v4(o + 8, c);
    red_add_v4(o + 12, w);
}

// variables1[v] = relu(onesWv + c2v1[v] @ Wv_bot + bv)   (top input row == ones)
__global__ void k_vars1(const float* __restrict__ Wv, const float* __restrict__ bv) {
    __shared__ float sW[F * F];   // bottom half of Wv
    __shared__ float sbase[F];    // bv[f] + sum_j Wv_top[j][f]
    for (int i = threadIdx.x; i < F * F; i += blockDim.x) sW[i] = Wv[F * F + i];
    if (threadIdx.x < F) {
        float s = bv[threadIdx.x];
#pragma unroll
        for (int j = 0; j < F; j++) s += Wv[j * F + threadIdx.x];
        sbase[threadIdx.x] = s;
    }
    __syncthreads();
    int v = blockIdx.x * blockDim.x + threadIdx.x;
    if (v >= NV) return;
    float x[F];
    load16(x, g_c2v1 + (size_t)v * F);
    float o[F];
#pragma unroll
    for (int f = 0; f < F; f++) {
        float acc = sbase[f];
#pragma unroll
        for (int j = 0; j < F; j++) acc = fmaf(x[j], sW[j * F + f], acc);
        o[f] = fmaxf(acc, 0.f);
    }
    store16(g_vars1 + (size_t)v * F, o);
}

// constraints2[c] = relu([cons1[c], v2c2[c]] @ Wc + bc)
__global__ void k_cons2(const float* __restrict__ Wc, const float* __restrict__ bc) {
    __shared__ float sW[2 * F * F];
    __shared__ float sb[F];
    for (int i = threadIdx.x; i < 2 * F * F; i += blockDim.x) sW[i] = Wc[i];
    if (threadIdx.x < F) sb[threadIdx.x] = bc[threadIdx.x];
    __syncthreads();
    int c = blockIdx.x * blockDim.x + threadIdx.x;
    if (c >= NC) return;
    float x[F], y[F];
    load16(x, g_cons1 + (size_t)c * F);
    load16(y, g_v2c2 + (size_t)c * F);
    float o[F];
#pragma unroll
    for (int f = 0; f < F; f++) {
        float acc = sb[f];
#pragma unroll
        for (int j = 0; j < F; j++) acc = fmaf(x[j], sW[j * F + f], acc);
#pragma unroll
        for (int j = 0; j < F; j++) acc = fmaf(y[j], sW[(F + j) * F + f], acc);
        o[f] = fmaxf(acc, 0.f);
    }
    store16(g_cons2 + (size_t)c * F, o);
}

// variables2 + output head + JAX noise + sigmoid, fully fused
__global__ void k_final(const float* __restrict__ Wv, const float* __restrict__ bv,
                        const float* __restrict__ Wo, const float* __restrict__ bo,
                        const float* __restrict__ Wo2, const float* __restrict__ bo2,
                        float* __restrict__ out) {
    __shared__ float sWv[2 * F * F], sWo[F * F], sWo2[F], sbv[F], sbo[F], sbo2;
    for (int i = threadIdx.x; i < 2 * F * F; i += blockDim.x) sWv[i] = Wv[i];
    for (int i = threadIdx.x; i < F * F; i += blockDim.x) sWo[i] = Wo[i];
    if (threadIdx.x < F) {
        sWo2[threadIdx.x] = Wo2[threadIdx.x];
        sbv[threadIdx.x] = bv[threadIdx.x];
        sbo[threadIdx.x] = bo[threadIdx.x];
    }
    if (threadIdx.x == 0) sbo2 = bo2[0];
    __syncthreads();
    int v = blockIdx.x * blockDim.x + threadIdx.x;
    if (v >= NV) return;

    float x[F], y[F];
    load16(x, g_vars1 + (size_t)v * F);
    load16(y, g_c2v2 + (size_t)v * F);

    float t[F];
#pragma unroll
    for (int f = 0; f < F; f++) {
        float acc = sbv[f];
#pragma unroll
        for (int j = 0; j < F; j++) acc = fmaf(x[j], sWv[j * F + f], acc);
#pragma unroll
        for (int j = 0; j < F; j++) acc = fmaf(y[j], sWv[(F + j) * F + f], acc);
        t[f] = fmaxf(acc, 0.f);
    }
    float h[F];
#pragma unroll
    for (int f = 0; f < F; f++) {
        float acc = sbo[f];
#pragma unroll
        for (int j = 0; j < F; j++) acc = fmaf(t[j], sWo[j * F + f], acc);
        h[f] = fmaxf(acc, 0.f);
    }
    float a = sbo2;
#pragma unroll
    for (int j = 0; j < F; j++) a = fmaf(h[j], sWo2[j], a);

    // JAX noise, PARTITIONABLE threefry (default-on in modern JAX):
    // per-element 64-bit flat counter i -> (x0, x1) = (hi32(i), lo32(i)) = (0, i),
    // 32-bit fold: bits = o0 ^ o1
    uint32_t o0, o1;
    threefry_0_42(0u, (uint32_t)v, o0, o1);
    uint32_t bits = o0 ^ o1;
    float f01 = __uint_as_float((bits >> 9) | 0x3f800000u) - 1.0f;  // [0,1)
    const float lo = -0.99999994f;  // nextafter(-1, 0)
    float u = f01 * 2.0f;           // (1 - lo) rounds to 2.0f (ties-to-even)
    u = u + lo;
    u = fmaxf(u, lo);
    float noise = 8.0f * (1.41421354f * erfinv_xla(u));

    float av = a + noise;
    out[v] = 1.0f / (1.0f + expf(-av));
}

// ---------------- launch ----------------
extern "C" void kernel_launch(void* const* d_in, const int* in_sizes, int n_in,
                              void* d_out, int out_size) {
    const int*   edge_rows = (const int*)d_in[0];
    const int*   edge_cols = (const int*)d_in[1];
    const float* edge_vals = (const float*)d_in[2];
    // d_in[3] = conditions_values (unused by the reference)
    const float* Wc  = (const float*)d_in[4];
    const float* bc  = (const float*)d_in[5];
    const float* Wv  = (const float*)d_in[6];
    const float* bv  = (const float*)d_in[7];
    const float* Wo  = (const float*)d_in[8];
    const float* bo  = (const float*)d_in[9];
    const float* Wo2 = (const float*)d_in[10];
    const float* bo2 = (const float*)d_in[11];
    float* out = (float*)d_out;

    void *p_colsum, *p_c2v1, *p_v2c2, *p_c2v2;
    void *p_cons1, *p_cons2, *p_vars1;
    cudaGetSymbolAddress(&p_colsum, g_colsum);
    cudaGetSymbolAddress(&p_c2v1,  g_c2v1);
    cudaGetSymbolAddress(&p_v2c2,  g_v2c2);
    cudaGetSymbolAddress(&p_c2v2,  g_c2v2);
    cudaGetSymbolAddress(&p_cons1, g_cons1);
    cudaGetSymbolAddress(&p_cons2, g_cons2);
    cudaGetSymbolAddress(&p_vars1, g_vars1);

    // zero the atomic-accumulation buffers
    cudaMemsetAsync(p_colsum, 0, NC * sizeof(float));
    cudaMemsetAsync(p_c2v1,  0, (size_t)NV * F * sizeof(float));
    cudaMemsetAsync(p_v2c2,  0, (size_t)NC * F * sizeof(float));
    cudaMemsetAsync(p_c2v2,  0, (size_t)NV * F * sizeof(float));

    const int T = 256;
    const int GE = (NE + T - 1) / T;
    const int GV = (NV + T - 1) / T;
    const int GC = (NC + T - 1) / T;

    // pass 1 (v2c collapsed to scalar colsum)
    k_colsum<<<GE, T>>>(edge_cols, edge_vals);
    k_cons1<<<GC, T>>>(Wc, bc);
    k_spmm<<<GE, T>>>(edge_cols, edge_rows, edge_vals, (const float*)p_cons1, (float*)p_c2v1);
    k_vars1<<<GV, T>>>(Wv, bv);

    // pass 2
    k_spmm<<<GE, T>>>(edge_rows, edge_cols, edge_vals, (const float*)p_vars1, (float*)p_v2c2);
    k_cons2<<<GC, T>>>(Wc, bc);
    k_spmm<<<GE, T>>>(edge_cols, edge_rows, edge_vals, (const float*)p_cons2, (float*)p_c2v2);

    // variables2 + output head + noise + sigmoid
    k_final<<<GV, T>>>(Wv, bv, Wo, bo, Wo2, bo2, out);
}

// round 3
// speedup vs baseline: 1.4386x; 1.4386x over previous
#include <cuda_runtime.h>
#include <cstdint>

#define NV 500000
#define NC 250000
#define NE 8000000
#define F  16

// ---------------- scratch (device globals: no allocation allowed) ----------------
__device__ __align__(16) float g_colsum[NC];
__device__ __align__(16) float g_swcb[2 * F];     // [0:16) swc  [16:32) base (bc)
__device__ __align__(16) float g_cons1[NC * F];
__device__ __align__(16) float g_cons2[NC * F];
__device__ __align__(16) float g_v2c2[NC * F];
__device__ __align__(16) float g_c2v1[NV * F];
__device__ __align__(16) float g_c2v2[NV * F];
__device__ __align__(16) float g_vars1[NV * F];

// ---------------- helpers ----------------
__device__ __forceinline__ void red_add_v4(float* a, float4 v) {
    asm volatile("red.global.add.v4.f32 [%0], {%1,%2,%3,%4};"
                 :: "l"(a), "f"(v.x), "f"(v.y), "f"(v.z), "f"(v.w) : "memory");
}

// JAX threefry2x32 with key = (0, 42)
__device__ __forceinline__ void threefry_0_42(uint32_t x0, uint32_t x1,
                                              uint32_t& o0, uint32_t& o1) {
    const uint32_t k0 = 0u, k1 = 42u;
    const uint32_t k2 = 0x1BD11BDAu ^ k0 ^ k1;
    x0 += k0; x1 += k1;
#define TFR(r) { x0 += x1; x1 = (x1 << (r)) | (x1 >> (32 - (r))); x1 ^= x0; }
    TFR(13) TFR(15) TFR(26) TFR(6)   x0 += k1; x1 += k2 + 1u;
    TFR(17) TFR(29) TFR(16) TFR(24)  x0 += k2; x1 += k0 + 2u;
    TFR(13) TFR(15) TFR(26) TFR(6)   x0 += k0; x1 += k1 + 3u;
    TFR(17) TFR(29) TFR(16) TFR(24)  x0 += k1; x1 += k2 + 4u;
    TFR(13) TFR(15) TFR(26) TFR(6)   x0 += k2; x1 += k0 + 5u;
#undef TFR
    o0 = x0; o1 = x1;
}

// XLA f32 ErfInv (Giles polynomial), matching lax.erf_inv
__device__ __forceinline__ float erfinv_xla(float x) {
    float w = -log1pf(-x * x);
    float p;
    if (w < 5.0f) {
        w -= 2.5f;
        p = 2.81022636e-08f;
        p = fmaf(p, w, 3.43273939e-07f);
        p = fmaf(p, w, -3.5233877e-06f);
        p = fmaf(p, w, -4.39150654e-06f);
        p = fmaf(p, w, 0.00021858087f);
        p = fmaf(p, w, -0.00125372503f);
        p = fmaf(p, w, -0.00417768164f);
        p = fmaf(p, w, 0.246640727f);
        p = fmaf(p, w, 1.50140941f);
    } else {
        w = sqrtf(w) - 3.0f;
        p = -0.000200214257f;
        p = fmaf(p, w, 0.000100950558f);
        p = fmaf(p, w, 0.00134934322f);
        p = fmaf(p, w, -0.00367342844f);
        p = fmaf(p, w, 0.00573950773f);
        p = fmaf(p, w, -0.0076224613f);
        p = fmaf(p, w, 0.00943887047f);
        p = fmaf(p, w, 1.00167406f);
        p = fmaf(p, w, 2.83297682f);
    }
    return p * x;
}

__device__ __forceinline__ void load16(float* x, const float* __restrict__ p) {
    const float4* r = (const float4*)p;
    float4 a = r[0], b = r[1], c = r[2], d = r[3];
    x[0]=a.x; x[1]=a.y; x[2]=a.z; x[3]=a.w;
    x[4]=b.x; x[5]=b.y; x[6]=b.z; x[7]=b.w;
    x[8]=c.x; x[9]=c.y; x[10]=c.z; x[11]=c.w;
    x[12]=d.x; x[13]=d.y; x[14]=d.z; x[15]=d.w;
}

__device__ __forceinline__ void store16(float* __restrict__ p, const float* x) {
    float4* w = (float4*)p;
    w[0] = make_float4(x[0], x[1], x[2], x[3]);
    w[1] = make_float4(x[4], x[5], x[6], x[7]);
    w[2] = make_float4(x[8], x[9], x[10], x[11]);
    w[3] = make_float4(x[12], x[13], x[14], x[15]);
}

// ---------------- kernels ----------------

// Pass-1 v2c collapses to a scalar column-sum (variables == ones)
__global__ void k_colsum(const int* __restrict__ cols, const float* __restrict__ vals) {
    int i = blockIdx.x * blockDim.x + threadIdx.x;
    if (i < NE) atomicAdd(&g_colsum[cols[i]], vals[i]);
}

// tiny prep: swc[f] = sum_j Wc_bot[j][f], base[f] = bc[f]
__global__ void k_prep(const float* __restrict__ Wc, const float* __restrict__ bc) {
    int f = threadIdx.x;
    if (f >= F) return;
    float s = 0.f;
#pragma unroll
    for (int j = 0; j < F; j++) s += Wc[(F + j) * F + f];
    g_swcb[f] = s;
    g_swcb[F + f] = bc[f];
}

// constraints1[c][f] = relu(colsum[c]*swc[f] + bc[f])  (materialized for cons2)
__global__ void k_cons1() {
    __shared__ float sw[F], sb[F];
    if (threadIdx.x < F) { sw[threadIdx.x] = g_swcb[threadIdx.x]; sb[threadIdx.x] = g_swcb[F + threadIdx.x]; }
    __syncthreads();
    int c = blockIdx.x * blockDim.x + threadIdx.x;
    if (c >= NC) return;
    float cs = g_colsum[c];
    float o[F];
#pragma unroll
    for (int f = 0; f < F; f++) o[f] = fmaxf(fmaf(cs, sw[f], sb[f]), 0.f);
    store16(g_cons1 + (size_t)c * F, o);
}

// SpMM pass 1 fused with on-the-fly cons1: gather SCALAR colsum[col], expand to
// features via rank-1 relu, scatter into c2v1[row]. Quarter-warp per edge.
__global__ void k_spmm1(const int* __restrict__ rows, const int* __restrict__ cols,
                        const float* __restrict__ vals) {
    __shared__ float sw[F], sb[F];
    if (threadIdx.x < F) { sw[threadIdx.x] = g_swcb[threadIdx.x]; sb[threadIdx.x] = g_swcb[F + threadIdx.x]; }
    __syncthreads();
    long long t = (long long)blockIdx.x * blockDim.x + threadIdx.x;
    int e = (int)(t >> 2), q = (int)(t & 3);
    if (e >= NE) return;
    float cs = __ldg(&g_colsum[__ldg(cols + e)]);
    float v = __ldg(vals + e);
    int d = __ldg(rows + e);
    int b = q * 4;
    float4 m;
    m.x = fmaxf(fmaf(cs, sw[b + 0], sb[b + 0]), 0.f) * v;
    m.y = fmaxf(fmaf(cs, sw[b + 1], sb[b + 1]), 0.f) * v;
    m.z = fmaxf(fmaf(cs, sw[b + 2], sb[b + 2]), 0.f) * v;
    m.w = fmaxf(fmaf(cs, sw[b + 3], sb[b + 3]), 0.f) * v;
    red_add_v4(g_c2v1 + (size_t)d * F + b, m);
}

// generic gather-scale-scatter, quarter-warp per edge:
// out[dst[e]][q*4..] += val[e] * tbl[src[e]][q*4..]
__global__ void k_spmm_q(const int* __restrict__ src, const int* __restrict__ dst,
                         const float* __restrict__ vals, const float* __restrict__ tbl,
                         float* __restrict__ out) {
    long long t = (long long)blockIdx.x * blockDim.x + threadIdx.x;
    int e = (int)(t >> 2), q = (int)(t & 3);
    if (e >= NE) return;
    int s = __ldg(src + e), d = __ldg(dst + e);
    float v = __ldg(vals + e);
    float4 r = __ldg((const float4*)(tbl + (size_t)s * F) + q);
    r.x *= v; r.y *= v; r.z *= v; r.w *= v;
    red_add_v4(out + (size_t)d * F + q * 4, r);
}

// variables1[v] = relu(onesWv + c2v1[v] @ Wv_bot + bv)
__global__ void k_vars1(const float* __restrict__ Wv, const float* __restrict__ bv) {
    __shared__ float sW[F * F];
    __shared__ float sbase[F];
    for (int i = threadIdx.x; i < F * F; i += blockDim.x) sW[i] = Wv[F * F + i];
    if (threadIdx.x < F) {
        float s = bv[threadIdx.x];
#pragma unroll
        for (int j = 0; j < F; j++) s += Wv[j * F + threadIdx.x];
        sbase[threadIdx.x] = s;
    }
    __syncthreads();
    int v = blockIdx.x * blockDim.x + threadIdx.x;
    if (v >= NV) return;
    float x[F];
    load16(x, g_c2v1 + (size_t)v * F);
    float o[F];
#pragma unroll
    for (int f = 0; f < F; f++) {
        float acc = sbase[f];
#pragma unroll
        for (int j = 0; j < F; j++) acc = fmaf(x[j], sW[j * F + f], acc);
        o[f] = fmaxf(acc, 0.f);
    }
    store16(g_vars1 + (size_t)v * F, o);
}

// constraints2[c] = relu([cons1[c], v2c2[c]] @ Wc + bc)
__global__ void k_cons2(const float* __restrict__ Wc, const float* __restrict__ bc) {
    __shared__ float sW[2 * F * F];
    __shared__ float sb[F];
    for (int i = threadIdx.x; i < 2 * F * F; i += blockDim.x) sW[i] = Wc[i];
    if (threadIdx.x < F) sb[threadIdx.x] = bc[threadIdx.x];
    __syncthreads();
    int c = blockIdx.x * blockDim.x + threadIdx.x;
    if (c >= NC) return;
    float x[F], y[F];
    load16(x, g_cons1 + (size_t)c * F);
    load16(y, g_v2c2 + (size_t)c * F);
    float o[F];
#pragma unroll
    for (int f = 0; f < F; f++) {
        float acc = sb[f];
#pragma unroll
        for (int j = 0; j < F; j++) acc = fmaf(x[j], sW[j * F + f], acc);
#pragma unroll
        for (int j = 0; j < F; j++) acc = fmaf(y[j], sW[(F + j) * F + f], acc);
        o[f] = fmaxf(acc, 0.f);
    }
    store16(g_cons2 + (size_t)c * F, o);
}

// variables2 + output head + JAX noise + sigmoid, fully fused
__global__ void k_final(const float* __restrict__ Wv, const float* __restrict__ bv,
                        const float* __restrict__ Wo, const float* __restrict__ bo,
                        const float* __restrict__ Wo2, const float* __restrict__ bo2,
                        float* __restrict__ out) {
    __shared__ float sWv[2 * F * F], sWo[F * F], sWo2[F], sbv[F], sbo[F], sbo2;
    for (int i = threadIdx.x; i < 2 * F * F; i += blockDim.x) sWv[i] = Wv[i];
    for (int i = threadIdx.x; i < F * F; i += blockDim.x) sWo[i] = Wo[i];
    if (threadIdx.x < F) {
        sWo2[threadIdx.x] = Wo2[threadIdx.x];
        sbv[threadIdx.x] = bv[threadIdx.x];
        sbo[threadIdx.x] = bo[threadIdx.x];
    }
    if (threadIdx.x == 0) sbo2 = bo2[0];
    __syncthreads();
    int v = blockIdx.x * blockDim.x + threadIdx.x;
    if (v >= NV) return;

    float x[F], y[F];
    load16(x, g_vars1 + (size_t)v * F);
    load16(y, g_c2v2 + (size_t)v * F);

    float t[F];
#pragma unroll
    for (int f = 0; f < F; f++) {
        float acc = sbv[f];
#pragma unroll
        for (int j = 0; j < F; j++) acc = fmaf(x[j], sWv[j * F + f], acc);
#pragma unroll
        for (int j = 0; j < F; j++) acc = fmaf(y[j], sWv[(F + j) * F + f], acc);
        t[f] = fmaxf(acc, 0.f);
    }
    float h[F];
#pragma unroll
    for (int f = 0; f < F; f++) {
        float acc = sbo[f];
#pragma unroll
        for (int j = 0; j < F; j++) acc = fmaf(t[j], sWo[j * F + f], acc);
        h[f] = fmaxf(acc, 0.f);
    }
    float a = sbo2;
#pragma unroll
    for (int j = 0; j < F; j++) a = fmaf(h[j], sWo2[j], a);

    // JAX noise, partitionable threefry: counter (0, v), fold bits = o0 ^ o1
    uint32_t o0, o1;
    threefry_0_42(0u, (uint32_t)v, o0, o1);
    uint32_t bits = o0 ^ o1;
    float f01 = __uint_as_float((bits >> 9) | 0x3f800000u) - 1.0f;  // [0,1)
    const float lo = -0.99999994f;  // nextafter(-1, 0)
    float u = f01 * 2.0f;
    u = u + lo;
    u = fmaxf(u, lo);
    float noise = 8.0f * (1.41421354f * erfinv_xla(u));

    float av = a + noise;
    out[v] = 1.0f / (1.0f + expf(-av));
}

// ---------------- launch ----------------
extern "C" void kernel_launch(void* const* d_in, const int* in_sizes, int n_in,
                              void* d_out, int out_size) {
    const int*   edge_rows = (const int*)d_in[0];
    const int*   edge_cols = (const int*)d_in[1];
    const float* edge_vals = (const float*)d_in[2];
    // d_in[3] = conditions_values (unused by the reference)
    const float* Wc  = (const float*)d_in[4];
    const float* bc  = (const float*)d_in[5];
    const float* Wv  = (const float*)d_in[6];
    const float* bv  = (const float*)d_in[7];
    const float* Wo  = (const float*)d_in[8];
    const float* bo  = (const float*)d_in[9];
    const float* Wo2 = (const float*)d_in[10];
    const float* bo2 = (const float*)d_in[11];
    float* out = (float*)d_out;

    void *p_colsum, *p_c2v1, *p_v2c2, *p_c2v2, *p_cons1, *p_cons2, *p_vars1;
    cudaGetSymbolAddress(&p_colsum, g_colsum);
    cudaGetSymbolAddress(&p_c2v1,  g_c2v1);
    cudaGetSymbolAddress(&p_v2c2,  g_v2c2);
    cudaGetSymbolAddress(&p_c2v2,  g_c2v2);
    cudaGetSymbolAddress(&p_cons1, g_cons1);
    cudaGetSymbolAddress(&p_cons2, g_cons2);
    cudaGetSymbolAddress(&p_vars1, g_vars1);

    // zero the atomic-accumulation buffers
    cudaMemsetAsync(p_colsum, 0, NC * sizeof(float));
    cudaMemsetAsync(p_c2v1,  0, (size_t)NV * F * sizeof(float));
    cudaMemsetAsync(p_v2c2,  0, (size_t)NC * F * sizeof(float));
    cudaMemsetAsync(p_c2v2,  0, (size_t)NV * F * sizeof(float));

    const int T = 256;
    const int GE  = (NE + T - 1) / T;                       // 1 thread / edge
    const long long TQ = 4LL * NE;                          // 4 threads / edge
    const int GEQ = (int)((TQ + T - 1) / T);
    const int GV = (NV + T - 1) / T;
    const int GC = (NC + T - 1) / T;

    // pass 1 (v2c collapsed to scalar colsum; cons1 fused into the gather)
    k_colsum<<<GE, T>>>(edge_cols, edge_vals);
    k_prep<<<1, 32>>>(Wc, bc);
    k_cons1<<<GC, T>>>();
    k_spmm1<<<GEQ, T>>>(edge_rows, edge_cols, edge_vals);
    k_vars1<<<GV, T>>>(Wv, bv);

    // pass 2
    k_spmm_q<<<GEQ, T>>>(edge_rows, edge_cols, edge_vals, (const float*)p_vars1, (float*)p_v2c2);
    k_cons2<<<GC, T>>>(Wc, bc);
    k_spmm_q<<<GEQ, T>>>(edge_cols, edge_rows, edge_vals, (const float*)p_cons2, (float*)p_c2v2);

    // variables2 + output head + noise + sigmoid
    k_final<<<GV, T>>>(Wv, bv, Wo, bo, Wo2, bo2, out);
}